// round 1
// baseline (speedup 1.0000x reference)
#include <cuda_runtime.h>
#include <math.h>

#define NV 3
#define NB 2
#define NC 64
#define NSC 32
#define NH 128
#define NW 128
#define HW (NH*NW)
#define NBLK_PIX (HW/256)   // 64 blocks of 256 threads per (b,s)

// Scratch (allocation-free): homography matrices + per-block partial sums.
__device__ float g_proj[(NV-1)*NB][12];          // [v-1][b]: 3x3 row-major M, then t (3)
__device__ float g_partial[NB*NSC*NBLK_PIX];     // per-block cost partial sums

__device__ __forceinline__ void mat3mul(const float* A, const float* B, float* C) {
    #pragma unroll
    for (int i = 0; i < 3; i++)
        #pragma unroll
        for (int j = 0; j < 3; j++)
            C[i*3+j] = A[i*3+0]*B[0*3+j] + A[i*3+1]*B[1*3+j] + A[i*3+2]*B[2*3+j];
}

__device__ __forceinline__ void mat3vec(const float* A, const float* v, float* r) {
    #pragma unroll
    for (int i = 0; i < 3; i++)
        r[i] = A[i*3+0]*v[0] + A[i*3+1]*v[1] + A[i*3+2]*v[2];
}

__device__ __forceinline__ void mat3inv(const float* A, float* Ai) {
    float a=A[0],b=A[1],c=A[2],d=A[3],e=A[4],f=A[5],g=A[6],h=A[7],i=A[8];
    float c00 =  (e*i - f*h);
    float c01 = -(d*i - f*g);
    float c02 =  (d*h - e*g);
    float det = a*c00 + b*c01 + c*c02;
    float inv = 1.0f / det;
    Ai[0] =  (e*i - f*h)*inv; Ai[1] = -(b*i - c*h)*inv; Ai[2] =  (b*f - c*e)*inv;
    Ai[3] = -(d*i - f*g)*inv; Ai[4] =  (a*i - c*g)*inv; Ai[5] = -(a*f - c*d)*inv;
    Ai[6] =  (d*h - e*g)*inv; Ai[7] = -(a*h - b*g)*inv; Ai[8] =  (a*e - b*d)*inv;
}

// ---------------------------------------------------------------------------
// Kernel 1: compute per-(view,batch) homography rot/trans.
// proj = src_P @ src_w2c @ inv(ref_P @ ref_w2c) where *_P is w2c with the
// rotation block replaced by K.  All matrices are [A|b; 0 0 0 1] form, so:
//   src_P @ src_w2c   = [Ks*RsT | Ks*tsw + tsw]
//   ref_P @ ref_w2c   = [Kr*RrT | Kr*trw + trw]   (invert closed-form)
// ---------------------------------------------------------------------------
__global__ void k_prep(const float* __restrict__ intr, const float* __restrict__ c2w) {
    int tid = threadIdx.x;
    if (tid >= (NV-1)*NB) return;
    int v = 1 + tid / NB;
    int b = tid % NB;

    const float* Kr = intr + (0*NB + b)*9;
    const float* Tr = c2w  + (0*NB + b)*16;
    const float* Ks = intr + (v*NB + b)*9;
    const float* Ts = c2w  + (v*NB + b)*16;

    float RrT[9], RsT[9], tr[3], ts[3];
    #pragma unroll
    for (int i = 0; i < 3; i++) {
        #pragma unroll
        for (int j = 0; j < 3; j++) {
            RrT[j*3+i] = Tr[i*4+j];   // transpose of c2w rotation = w2c rotation
            RsT[j*3+i] = Ts[i*4+j];
        }
        tr[i] = Tr[i*4+3];
        ts[i] = Ts[i*4+3];
    }
    float trw[3], tsw[3], tmp[3];
    mat3vec(RrT, tr, tmp); trw[0]=-tmp[0]; trw[1]=-tmp[1]; trw[2]=-tmp[2];
    mat3vec(RsT, ts, tmp); tsw[0]=-tmp[0]; tsw[1]=-tmp[1]; tsw[2]=-tmp[2];

    // Ref side: A = Kr*RrT, bref = Kr*trw + trw
    float A[9], bref[3], Ai[9];
    mat3mul(Kr, RrT, A);
    mat3vec(Kr, trw, tmp);
    bref[0]=tmp[0]+trw[0]; bref[1]=tmp[1]+trw[1]; bref[2]=tmp[2]+trw[2];
    mat3inv(A, Ai);

    // Src side: SM = Ks*RsT, St = Ks*tsw + tsw
    float SM[9], St[3];
    mat3mul(Ks, RsT, SM);
    mat3vec(Ks, tsw, tmp);
    St[0]=tmp[0]+tsw[0]; St[1]=tmp[1]+tsw[1]; St[2]=tmp[2]+tsw[2];

    // proj = [SM*Ai | St - (SM*Ai)*bref]
    float M[9], Mb[3];
    mat3mul(SM, Ai, M);
    mat3vec(M, bref, Mb);

    float* out = g_proj[(v-1)*NB + b];
    #pragma unroll
    for (int i = 0; i < 9; i++) out[i] = M[i];
    out[9]  = St[0] - Mb[0];
    out[10] = St[1] - Mb[1];
    out[11] = St[2] - Mb[2];
}

// ---------------------------------------------------------------------------
// Kernel 2: main cost-volume kernel.
// grid = (HW/256, NS, B); each thread = one (y,x) pixel at one (b,s).
// ---------------------------------------------------------------------------
__global__ void __launch_bounds__(256) k_main(const float* __restrict__ feat,
                                             const float* __restrict__ scale_hypo,
                                             const float* __restrict__ depth_init) {
    const int b = blockIdx.z;
    const int s = blockIdx.y;
    const int pix = blockIdx.x * 256 + threadIdx.x;
    const int x = pix & (NW - 1);
    const int y = pix >> 7;
    const float fx = (float)x;
    const float fy = (float)y;

    const float d = depth_init[b*HW + pix] * scale_hypo[b*NSC + s];

    float w[2][4];
    int   off[2][4];

    #pragma unroll
    for (int vv = 0; vv < 2; vv++) {
        const float* P = g_proj[vv*NB + b];
        float m0 = P[0]*fx + P[1]*fy + P[2];
        float m1 = P[3]*fx + P[4]*fy + P[5];
        float m2 = P[6]*fx + P[7]*fy + P[8];
        float px = m0*d + P[9];
        float py = m1*d + P[10];
        float pz = m2*d + P[11];
        float invz = 1.0f / pz;
        // Match reference arithmetic: gx = (px/pz)/((W-1)/2) - 1; ix = ((gx+1)*W - 1)*0.5
        float gx = (px*invz) * (2.0f/(NW-1)) - 1.0f;
        float gy = (py*invz) * (2.0f/(NH-1)) - 1.0f;
        float ix = ((gx + 1.0f) * NW - 1.0f) * 0.5f;
        float iy = ((gy + 1.0f) * NH - 1.0f) * 0.5f;

        float x0f = floorf(ix), y0f = floorf(iy);
        float x1f = x0f + 1.0f, y1f = y0f + 1.0f;
        float wx1 = ix - x0f, wx0 = 1.0f - wx1;
        float wy1 = iy - y0f, wy0 = 1.0f - wy1;

        float vx0 = (x0f >= 0.0f && x0f <= (float)(NW-1)) ? 1.0f : 0.0f;
        float vx1 = (x1f >= 0.0f && x1f <= (float)(NW-1)) ? 1.0f : 0.0f;
        float vy0 = (y0f >= 0.0f && y0f <= (float)(NH-1)) ? 1.0f : 0.0f;
        float vy1 = (y1f >= 0.0f && y1f <= (float)(NH-1)) ? 1.0f : 0.0f;

        int x0 = (int)fminf(fmaxf(x0f, 0.0f), (float)(NW-1));
        int x1 = (int)fminf(fmaxf(x1f, 0.0f), (float)(NW-1));
        int y0 = (int)fminf(fmaxf(y0f, 0.0f), (float)(NH-1));
        int y1 = (int)fminf(fmaxf(y1f, 0.0f), (float)(NH-1));

        off[vv][0] = y0*NW + x0;  w[vv][0] = wx0*wy0*vx0*vy0;
        off[vv][1] = y0*NW + x1;  w[vv][1] = wx1*wy0*vx1*vy0;
        off[vv][2] = y1*NW + x0;  w[vv][2] = wx0*wy1*vx0*vy1;
        off[vv][3] = y1*NW + x1;  w[vv][3] = wx1*wy1*vx1*vy1;
    }

    const float* p0 = feat + (size_t)(0*NB + b)*NC*HW + pix;
    const float* p1 = feat + (size_t)(1*NB + b)*NC*HW;
    const float* p2 = feat + (size_t)(2*NB + b)*NC*HW;

    float acc1 = 0.0f, acc2 = 0.0f;
    #pragma unroll 4
    for (int c = 0; c < NC; c++) {
        float a = p0[0];
        float s1 =      p1[off[0][0]] * w[0][0];
        s1 = fmaf(p1[off[0][1]], w[0][1], s1);
        s1 = fmaf(p1[off[0][2]], w[0][2], s1);
        s1 = fmaf(p1[off[0][3]], w[0][3], s1);
        float r1 = a - s1;
        acc1 = fmaf(r1, r1, acc1);

        float s2 =      p2[off[1][0]] * w[1][0];
        s2 = fmaf(p2[off[1][1]], w[1][1], s2);
        s2 = fmaf(p2[off[1][2]], w[1][2], s2);
        s2 = fmaf(p2[off[1][3]], w[1][3], s2);
        float r2 = r1 - s2;
        acc2 = fmaf(r2, r2, acc2);

        p0 += HW; p1 += HW; p2 += HW;
    }

    float cp = sqrtf(acc1) + sqrtf(acc2);

    // Block reduction (warp shuffle + shared across 8 warps)
    #pragma unroll
    for (int o = 16; o > 0; o >>= 1)
        cp += __shfl_xor_sync(0xffffffffu, cp, o);

    __shared__ float sh[8];
    int lane = threadIdx.x & 31;
    int wid  = threadIdx.x >> 5;
    if (lane == 0) sh[wid] = cp;
    __syncthreads();
    if (wid == 0) {
        float v = (lane < 8) ? sh[lane] : 0.0f;
        #pragma unroll
        for (int o = 4; o > 0; o >>= 1)
            v += __shfl_xor_sync(0xffffffffu, v, o);
        if (lane == 0)
            g_partial[(b*NSC + s)*NBLK_PIX + blockIdx.x] = v;
    }
}

// ---------------------------------------------------------------------------
// Kernel 3: reduce partials, softmax over scales, weighted scale sum.
// 64 threads: warp = one batch, lane = one scale.
// ---------------------------------------------------------------------------
__global__ void k_final(const float* __restrict__ scale_hypo, float* __restrict__ out) {
    int t = threadIdx.x;
    if (t >= NB*NSC) return;
    int b = t >> 5;
    int s = t & 31;

    const float* p = g_partial + (b*NSC + s)*NBLK_PIX;
    float sum = 0.0f;
    #pragma unroll
    for (int i = 0; i < NBLK_PIX; i++) sum += p[i];
    float cost = sum * (1.0f / (2.0f * (float)HW));   // /(V-1) then mean over H*W

    float m = cost;
    #pragma unroll
    for (int o = 16; o > 0; o >>= 1)
        m = fmaxf(m, __shfl_xor_sync(0xffffffffu, m, o));
    float e = expf(cost - m);
    float sc = scale_hypo[b*NSC + s];
    float den = e, num = e * sc;
    #pragma unroll
    for (int o = 16; o > 0; o >>= 1) {
        den += __shfl_xor_sync(0xffffffffu, den, o);
        num += __shfl_xor_sync(0xffffffffu, num, o);
    }
    if (s == 0) out[b] = num / den;
}

extern "C" void kernel_launch(void* const* d_in, const int* in_sizes, int n_in,
                              void* d_out, int out_size) {
    const float* feat  = (const float*)d_in[0];   // (V,B,C,H,W)
    const float* intr  = (const float*)d_in[1];   // (V,B,3,3)
    const float* c2w   = (const float*)d_in[2];   // (V,B,4,4)
    const float* scale = (const float*)d_in[3];   // (B,NS)
    const float* depth = (const float*)d_in[4];   // (B,H,W)
    float* out = (float*)d_out;                   // (B,)

    k_prep<<<1, 32>>>(intr, c2w);
    dim3 grid(NBLK_PIX, NSC, NB);
    k_main<<<grid, 256>>>(feat, scale, depth);
    k_final<<<1, 64>>>(scale, out);
}

// round 2
// speedup vs baseline: 1.4045x; 1.4045x over previous
#include <cuda_runtime.h>
#include <math.h>

#define NV 3
#define NB 2
#define NC 64
#define NSC 32
#define NH 128
#define NW 128
#define HW (NH*NW)
#define PIX_PER_BLK 32              // 256 threads, 8 lanes per pixel
#define GRIDX (HW/PIX_PER_BLK)      // 512

// Allocation-free scratch.
__device__ float g_proj[(NV-1)*NB][12];        // [v-1][b]: 3x3 M row-major, then t
__device__ float g_partial[NB*NSC*GRIDX];      // per-block cost partials
__device__ float g_ft[(size_t)NV*NB*NC*HW];    // features transposed to (V,B,H,W,C)

__device__ __forceinline__ void mat3mul(const float* A, const float* B, float* C) {
    #pragma unroll
    for (int i = 0; i < 3; i++)
        #pragma unroll
        for (int j = 0; j < 3; j++)
            C[i*3+j] = A[i*3+0]*B[0*3+j] + A[i*3+1]*B[1*3+j] + A[i*3+2]*B[2*3+j];
}
__device__ __forceinline__ void mat3vec(const float* A, const float* v, float* r) {
    #pragma unroll
    for (int i = 0; i < 3; i++)
        r[i] = A[i*3+0]*v[0] + A[i*3+1]*v[1] + A[i*3+2]*v[2];
}
__device__ __forceinline__ void mat3inv(const float* A, float* Ai) {
    float a=A[0],b=A[1],c=A[2],d=A[3],e=A[4],f=A[5],g=A[6],h=A[7],i=A[8];
    float det = a*(e*i-f*h) - b*(d*i-f*g) + c*(d*h-e*g);
    float inv = 1.0f / det;
    Ai[0] =  (e*i - f*h)*inv; Ai[1] = -(b*i - c*h)*inv; Ai[2] =  (b*f - c*e)*inv;
    Ai[3] = -(d*i - f*g)*inv; Ai[4] =  (a*i - c*g)*inv; Ai[5] = -(a*f - c*d)*inv;
    Ai[6] =  (d*h - e*g)*inv; Ai[7] = -(a*h - b*g)*inv; Ai[8] =  (a*e - b*d)*inv;
}

// ---------------------------------------------------------------------------
// Homography precompute (unchanged from R1, verified rel_err 2.4e-7).
// ---------------------------------------------------------------------------
__global__ void k_prep(const float* __restrict__ intr, const float* __restrict__ c2w) {
    int tid = threadIdx.x;
    if (tid >= (NV-1)*NB) return;
    int v = 1 + tid / NB;
    int b = tid % NB;

    const float* Kr = intr + (0*NB + b)*9;
    const float* Tr = c2w  + (0*NB + b)*16;
    const float* Ks = intr + (v*NB + b)*9;
    const float* Ts = c2w  + (v*NB + b)*16;

    float RrT[9], RsT[9], tr[3], ts[3];
    #pragma unroll
    for (int i = 0; i < 3; i++) {
        #pragma unroll
        for (int j = 0; j < 3; j++) {
            RrT[j*3+i] = Tr[i*4+j];
            RsT[j*3+i] = Ts[i*4+j];
        }
        tr[i] = Tr[i*4+3];
        ts[i] = Ts[i*4+3];
    }
    float trw[3], tsw[3], tmp[3];
    mat3vec(RrT, tr, tmp); trw[0]=-tmp[0]; trw[1]=-tmp[1]; trw[2]=-tmp[2];
    mat3vec(RsT, ts, tmp); tsw[0]=-tmp[0]; tsw[1]=-tmp[1]; tsw[2]=-tmp[2];

    float A[9], bref[3], Ai[9];
    mat3mul(Kr, RrT, A);
    mat3vec(Kr, trw, tmp);
    bref[0]=tmp[0]+trw[0]; bref[1]=tmp[1]+trw[1]; bref[2]=tmp[2]+trw[2];
    mat3inv(A, Ai);

    float SM[9], St[3];
    mat3mul(Ks, RsT, SM);
    mat3vec(Ks, tsw, tmp);
    St[0]=tmp[0]+tsw[0]; St[1]=tmp[1]+tsw[1]; St[2]=tmp[2]+tsw[2];

    float M[9], Mb[3];
    mat3mul(SM, Ai, M);
    mat3vec(M, bref, Mb);

    float* out = g_proj[(v-1)*NB + b];
    #pragma unroll
    for (int i = 0; i < 9; i++) out[i] = M[i];
    out[9]  = St[0] - Mb[0];
    out[10] = St[1] - Mb[1];
    out[11] = St[2] - Mb[2];
}

// ---------------------------------------------------------------------------
// Transpose (C, HW) -> (HW, C) per (v,b).  grid (HW/32, V*B), 256 threads.
// Reads coalesced along hw, writes coalesced along c (smem staged).
// ---------------------------------------------------------------------------
__global__ void __launch_bounds__(256) k_tr(const float* __restrict__ feat) {
    __shared__ float t[NC][33];
    const int vb  = blockIdx.y;
    const int hw0 = blockIdx.x * 32;
    const float* src = feat + (size_t)vb * NC * HW;
    float*       dst = g_ft + (size_t)vb * NC * HW;

    #pragma unroll
    for (int i = threadIdx.x; i < NC*32; i += 256) {
        int c = i >> 5, hw = i & 31;
        t[c][hw] = src[(size_t)c * HW + hw0 + hw];
    }
    __syncthreads();
    #pragma unroll
    for (int i = threadIdx.x; i < 32*NC; i += 256) {
        int hw = i >> 6, c = i & 63;
        dst[(size_t)(hw0 + hw) * NC + c] = t[c][hw];
    }
}

// ---------------------------------------------------------------------------
// Main cost-volume kernel.
// Block = 256 threads = 32 pixels (8 lanes/pixel, 4ch float4 x2 per lane).
// Scales looped inside; ref load + homography row-vectors hoisted.
// ---------------------------------------------------------------------------
__global__ void __launch_bounds__(256) k_main(const float* __restrict__ scale_hypo,
                                             const float* __restrict__ depth_init) {
    const int b   = blockIdx.y;
    const int tid = threadIdx.x;
    const int w   = tid >> 5;
    const int l   = tid & 31;
    const int pg  = (w << 2) | (l >> 3);        // pixel in block 0..31
    const int cl  = l & 7;                      // channel chunk 0..7
    const int pix = blockIdx.x * PIX_PER_BLK + pg;
    const float fx = (float)(pix & (NW-1));
    const float fy = (float)(pix >> 7);

    __shared__ float s_scale[NSC];
    __shared__ float s_part[NSC][8];
    if (tid < NSC) s_scale[tid] = scale_hypo[b*NSC + tid];
    __syncthreads();

    const float4* f0 = (const float4*)(g_ft + (size_t)(0*NB + b)*NC*HW);
    const float4* f1 = (const float4*)(g_ft + (size_t)(1*NB + b)*NC*HW) + cl;
    const float4* f2 = (const float4*)(g_ft + (size_t)(2*NB + b)*NC*HW) + cl;

    const float4 r0a = f0[pix*16 + cl];
    const float4 r0b = f0[pix*16 + 8 + cl];
    const float  d0  = depth_init[b*HW + pix];

    // s-invariant homography row vectors: m = M @ [x,y,1]
    const float* P1 = g_proj[0*NB + b];
    const float* P2 = g_proj[1*NB + b];
    const float m10 = P1[0]*fx + P1[1]*fy + P1[2];
    const float m11 = P1[3]*fx + P1[4]*fy + P1[5];
    const float m12 = P1[6]*fx + P1[7]*fy + P1[8];
    const float t10 = P1[9],  t11 = P1[10], t12 = P1[11];
    const float m20 = P2[0]*fx + P2[1]*fy + P2[2];
    const float m21 = P2[3]*fx + P2[4]*fy + P2[5];
    const float m22 = P2[6]*fx + P2[7]*fy + P2[8];
    const float t20 = P2[9],  t21 = P2[10], t22 = P2[11];

    const float CX = (float)NW / (float)(NW-1);
    const float CY = (float)NH / (float)(NH-1);

    #pragma unroll 1
    for (int s = 0; s < NSC; s++) {
        const float d = d0 * s_scale[s];
        float wt[8];
        int   of[8];

        // -- tap setup for both views --
        #pragma unroll
        for (int vv = 0; vv < 2; vv++) {
            float px = vv ? fmaf(m20, d, t20) : fmaf(m10, d, t10);
            float py = vv ? fmaf(m21, d, t21) : fmaf(m11, d, t11);
            float pz = vv ? fmaf(m22, d, t22) : fmaf(m12, d, t12);
            float rz = __fdividef(1.0f, pz);
            float ix = fmaf(px*rz, CX, -0.5f);
            float iy = fmaf(py*rz, CY, -0.5f);
            float x0f = floorf(ix), y0f = floorf(iy);
            float x1f = x0f + 1.0f, y1f = y0f + 1.0f;
            float wx1 = ix - x0f, wx0 = 1.0f - wx1;
            float wy1 = iy - y0f, wy0 = 1.0f - wy1;
            float vx0 = (x0f >= 0.0f && x0f <= (float)(NW-1)) ? 1.0f : 0.0f;
            float vx1 = (x1f >= 0.0f && x1f <= (float)(NW-1)) ? 1.0f : 0.0f;
            float vy0 = (y0f >= 0.0f && y0f <= (float)(NH-1)) ? 1.0f : 0.0f;
            float vy1 = (y1f >= 0.0f && y1f <= (float)(NH-1)) ? 1.0f : 0.0f;
            int x0 = (int)fminf(fmaxf(x0f, 0.0f), (float)(NW-1));
            int x1 = (int)fminf(fmaxf(x1f, 0.0f), (float)(NW-1));
            int y0 = (int)fminf(fmaxf(y0f, 0.0f), (float)(NH-1));
            int y1 = (int)fminf(fmaxf(y1f, 0.0f), (float)(NH-1));
            wt[vv*4+0] = wx0*wy0*vx0*vy0;  of[vv*4+0] = ((y0<<7) + x0) << 4;
            wt[vv*4+1] = wx1*wy0*vx1*vy0;  of[vv*4+1] = ((y0<<7) + x1) << 4;
            wt[vv*4+2] = wx0*wy1*vx0*vy1;  of[vv*4+2] = ((y1<<7) + x0) << 4;
            wt[vv*4+3] = wx1*wy1*vx1*vy1;  of[vv*4+3] = ((y1<<7) + x1) << 4;
        }

        // -- view 1 interpolate + residual --
        float4 Aa = make_float4(0.f,0.f,0.f,0.f);
        float4 Ab = make_float4(0.f,0.f,0.f,0.f);
        #pragma unroll
        for (int t = 0; t < 4; t++) {
            float4 ta = f1[of[t]];
            float4 tb = f1[of[t] + 8];
            float  ww = wt[t];
            Aa.x = fmaf(ta.x, ww, Aa.x); Aa.y = fmaf(ta.y, ww, Aa.y);
            Aa.z = fmaf(ta.z, ww, Aa.z); Aa.w = fmaf(ta.w, ww, Aa.w);
            Ab.x = fmaf(tb.x, ww, Ab.x); Ab.y = fmaf(tb.y, ww, Ab.y);
            Ab.z = fmaf(tb.z, ww, Ab.z); Ab.w = fmaf(tb.w, ww, Ab.w);
        }
        float4 r1a, r1b;
        r1a.x = r0a.x - Aa.x; r1a.y = r0a.y - Aa.y; r1a.z = r0a.z - Aa.z; r1a.w = r0a.w - Aa.w;
        r1b.x = r0b.x - Ab.x; r1b.y = r0b.y - Ab.y; r1b.z = r0b.z - Ab.z; r1b.w = r0b.w - Ab.w;
        float acc1 = r1a.x*r1a.x + r1a.y*r1a.y + r1a.z*r1a.z + r1a.w*r1a.w
                   + r1b.x*r1b.x + r1b.y*r1b.y + r1b.z*r1b.z + r1b.w*r1b.w;

        // -- view 2 interpolate + residual --
        float4 Ba = make_float4(0.f,0.f,0.f,0.f);
        float4 Bb = make_float4(0.f,0.f,0.f,0.f);
        #pragma unroll
        for (int t = 0; t < 4; t++) {
            float4 ta = f2[of[4+t]];
            float4 tb = f2[of[4+t] + 8];
            float  ww = wt[4+t];
            Ba.x = fmaf(ta.x, ww, Ba.x); Ba.y = fmaf(ta.y, ww, Ba.y);
            Ba.z = fmaf(ta.z, ww, Ba.z); Ba.w = fmaf(ta.w, ww, Ba.w);
            Bb.x = fmaf(tb.x, ww, Bb.x); Bb.y = fmaf(tb.y, ww, Bb.y);
            Bb.z = fmaf(tb.z, ww, Bb.z); Bb.w = fmaf(tb.w, ww, Bb.w);
        }
        float4 r2a, r2b;
        r2a.x = r1a.x - Ba.x; r2a.y = r1a.y - Ba.y; r2a.z = r1a.z - Ba.z; r2a.w = r1a.w - Ba.w;
        r2b.x = r1b.x - Bb.x; r2b.y = r1b.y - Bb.y; r2b.z = r1b.z - Bb.z; r2b.w = r1b.w - Bb.w;
        float acc2 = r2a.x*r2a.x + r2a.y*r2a.y + r2a.z*r2a.z + r2a.w*r2a.w
                   + r2b.x*r2b.x + r2b.y*r2b.y + r2b.z*r2b.z + r2b.w*r2b.w;

        // reduce across 8 channel lanes (aligned xor groups)
        #pragma unroll
        for (int o = 4; o > 0; o >>= 1) {
            acc1 += __shfl_xor_sync(0xffffffffu, acc1, o);
            acc2 += __shfl_xor_sync(0xffffffffu, acc2, o);
        }
        float cst = sqrtf(acc1) + sqrtf(acc2);
        // sum the warp's 4 pixels
        cst += __shfl_xor_sync(0xffffffffu, cst, 8);
        cst += __shfl_xor_sync(0xffffffffu, cst, 16);
        if (l == 0) s_part[s][w] = cst;
    }

    __syncthreads();
    if (tid < NSC) {
        float v = 0.0f;
        #pragma unroll
        for (int i = 0; i < 8; i++) v += s_part[tid][i];
        g_partial[(b*NSC + tid)*GRIDX + blockIdx.x] = v;
    }
}

// ---------------------------------------------------------------------------
// Final: reduce partials, softmax over scales, weighted sum.
// ---------------------------------------------------------------------------
__global__ void k_final(const float* __restrict__ scale_hypo, float* __restrict__ out) {
    int t = threadIdx.x;
    if (t >= NB*NSC) return;
    int b = t >> 5;
    int s = t & 31;

    const float* p = g_partial + (b*NSC + s)*GRIDX;
    float sum = 0.0f;
    for (int i = 0; i < GRIDX; i++) sum += p[i];
    float cost = sum * (1.0f / (2.0f * (float)HW));

    float m = cost;
    #pragma unroll
    for (int o = 16; o > 0; o >>= 1)
        m = fmaxf(m, __shfl_xor_sync(0xffffffffu, m, o));
    float e = expf(cost - m);
    float sc = scale_hypo[b*NSC + s];
    float den = e, num = e * sc;
    #pragma unroll
    for (int o = 16; o > 0; o >>= 1) {
        den += __shfl_xor_sync(0xffffffffu, den, o);
        num += __shfl_xor_sync(0xffffffffu, num, o);
    }
    if (s == 0) out[b] = num / den;
}

extern "C" void kernel_launch(void* const* d_in, const int* in_sizes, int n_in,
                              void* d_out, int out_size) {
    const float* feat  = (const float*)d_in[0];   // (V,B,C,H,W)
    const float* intr  = (const float*)d_in[1];   // (V,B,3,3)
    const float* c2w   = (const float*)d_in[2];   // (V,B,4,4)
    const float* scale = (const float*)d_in[3];   // (B,NS)
    const float* depth = (const float*)d_in[4];   // (B,H,W)
    float* out = (float*)d_out;                   // (B,)

    k_prep<<<1, 32>>>(intr, c2w);
    dim3 trg(HW/32, NV*NB);
    k_tr<<<trg, 256>>>(feat);
    dim3 grid(GRIDX, NB);
    k_main<<<grid, 256>>>(scale, depth);
    k_final<<<1, 64>>>(scale, out);
}

// round 3
// speedup vs baseline: 1.7757x; 1.2643x over previous
#include <cuda_runtime.h>
#include <cuda_fp16.h>
#include <math.h>

#define NV 3
#define NB 2
#define NC 64
#define NSC 32
#define NH 128
#define NW 128
#define HW (NH*NW)
#define PIX_PER_BLK 32              // 256 threads, 8 lanes per pixel
#define GRIDX (HW/PIX_PER_BLK)      // 512

// Allocation-free scratch.
__device__ float  g_proj[(NV-1)*NB][12];          // [v-1][b]: 3x3 M row-major, then t
__device__ float  g_partial[NB*NSC*GRIDX];        // per-block cost partials
__device__ float  g_cost[NB*NSC];                 // reduced costs
__device__ float  g_f0t[(size_t)NB*HW*NC];        // view0 transposed (B,HW,C) fp32
__device__ __half2 g_fht[(size_t)(NV-1)*NB*HW*(NC/2)]; // views 1,2 transposed fp16

__device__ __forceinline__ void mat3mul(const float* A, const float* B, float* C) {
    #pragma unroll
    for (int i = 0; i < 3; i++)
        #pragma unroll
        for (int j = 0; j < 3; j++)
            C[i*3+j] = A[i*3+0]*B[0*3+j] + A[i*3+1]*B[1*3+j] + A[i*3+2]*B[2*3+j];
}
__device__ __forceinline__ void mat3vec(const float* A, const float* v, float* r) {
    #pragma unroll
    for (int i = 0; i < 3; i++)
        r[i] = A[i*3+0]*v[0] + A[i*3+1]*v[1] + A[i*3+2]*v[2];
}
__device__ __forceinline__ void mat3inv(const float* A, float* Ai) {
    float a=A[0],b=A[1],c=A[2],d=A[3],e=A[4],f=A[5],g=A[6],h=A[7],i=A[8];
    float det = a*(e*i-f*h) - b*(d*i-f*g) + c*(d*h-e*g);
    float inv = 1.0f / det;
    Ai[0] =  (e*i - f*h)*inv; Ai[1] = -(b*i - c*h)*inv; Ai[2] =  (b*f - c*e)*inv;
    Ai[3] = -(d*i - f*g)*inv; Ai[4] =  (a*i - c*g)*inv; Ai[5] = -(a*f - c*d)*inv;
    Ai[6] =  (d*h - e*g)*inv; Ai[7] = -(a*h - b*g)*inv; Ai[8] =  (a*e - b*d)*inv;
}

// ---------------------------------------------------------------------------
// Homography precompute (verified).
// ---------------------------------------------------------------------------
__global__ void k_prep(const float* __restrict__ intr, const float* __restrict__ c2w) {
    int tid = threadIdx.x;
    if (tid >= (NV-1)*NB) return;
    int v = 1 + tid / NB;
    int b = tid % NB;

    const float* Kr = intr + (0*NB + b)*9;
    const float* Tr = c2w  + (0*NB + b)*16;
    const float* Ks = intr + (v*NB + b)*9;
    const float* Ts = c2w  + (v*NB + b)*16;

    float RrT[9], RsT[9], tr[3], ts[3];
    #pragma unroll
    for (int i = 0; i < 3; i++) {
        #pragma unroll
        for (int j = 0; j < 3; j++) {
            RrT[j*3+i] = Tr[i*4+j];
            RsT[j*3+i] = Ts[i*4+j];
        }
        tr[i] = Tr[i*4+3];
        ts[i] = Ts[i*4+3];
    }
    float trw[3], tsw[3], tmp[3];
    mat3vec(RrT, tr, tmp); trw[0]=-tmp[0]; trw[1]=-tmp[1]; trw[2]=-tmp[2];
    mat3vec(RsT, ts, tmp); tsw[0]=-tmp[0]; tsw[1]=-tmp[1]; tsw[2]=-tmp[2];

    float A[9], bref[3], Ai[9];
    mat3mul(Kr, RrT, A);
    mat3vec(Kr, trw, tmp);
    bref[0]=tmp[0]+trw[0]; bref[1]=tmp[1]+trw[1]; bref[2]=tmp[2]+trw[2];
    mat3inv(A, Ai);

    float SM[9], St[3];
    mat3mul(Ks, RsT, SM);
    mat3vec(Ks, tsw, tmp);
    St[0]=tmp[0]+tsw[0]; St[1]=tmp[1]+tsw[1]; St[2]=tmp[2]+tsw[2];

    float M[9], Mb[3];
    mat3mul(SM, Ai, M);
    mat3vec(M, bref, Mb);

    float* out = g_proj[(v-1)*NB + b];
    #pragma unroll
    for (int i = 0; i < 9; i++) out[i] = M[i];
    out[9]  = St[0] - Mb[0];
    out[10] = St[1] - Mb[1];
    out[11] = St[2] - Mb[2];
}

// ---------------------------------------------------------------------------
// Transpose (C, HW) -> (HW, C) per (v,b).  View 0: fp32 out. Views 1,2: fp16.
// grid (HW/32, V*B), 256 threads.
// ---------------------------------------------------------------------------
__global__ void __launch_bounds__(256) k_tr(const float* __restrict__ feat) {
    __shared__ float t[NC][33];
    const int vb  = blockIdx.y;
    const int v   = vb / NB;
    const int b   = vb % NB;
    const int hw0 = blockIdx.x * 32;
    const float* src = feat + (size_t)vb * NC * HW;

    #pragma unroll
    for (int i = threadIdx.x; i < NC*32; i += 256) {
        int c = i >> 5, hw = i & 31;
        t[c][hw] = src[(size_t)c * HW + hw0 + hw];
    }
    __syncthreads();

    if (v == 0) {
        float* dst = g_f0t + (size_t)b * HW * NC;
        #pragma unroll
        for (int i = threadIdx.x; i < 32*NC; i += 256) {
            int hw = i >> 6, c = i & 63;
            dst[(size_t)(hw0 + hw) * NC + c] = t[c][hw];
        }
    } else {
        __half2* dst = g_fht + (size_t)((v-1)*NB + b) * HW * (NC/2);
        #pragma unroll
        for (int i = threadIdx.x; i < 32*(NC/2); i += 256) {
            int hw = i >> 5, cp = i & 31;
            dst[(size_t)(hw0 + hw) * (NC/2) + cp] =
                __floats2half2_rn(t[2*cp][hw], t[2*cp+1][hw]);
        }
    }
}

// ---------------------------------------------------------------------------
// Main cost-volume kernel. Block = 256 threads = 32 pixels (8 lanes/pixel).
// Each warped tap: ONE 128B line (64 ch fp16); lane cl loads 16B = 8 channels.
// ---------------------------------------------------------------------------
__global__ void __launch_bounds__(256) k_main(const float* __restrict__ scale_hypo,
                                             const float* __restrict__ depth_init) {
    const int b   = blockIdx.y;
    const int tid = threadIdx.x;
    const int w   = tid >> 5;
    const int l   = tid & 31;
    const int pg  = (w << 2) | (l >> 3);        // pixel in block 0..31
    const int cl  = l & 7;                      // channel chunk 0..7 (8 ch each)
    const int pix = blockIdx.x * PIX_PER_BLK + pg;
    const float fx = (float)(pix & (NW-1));
    const float fy = (float)(pix >> 7);

    __shared__ float s_scale[NSC];
    __shared__ float s_part[NSC][8];
    if (tid < NSC) s_scale[tid] = scale_hypo[b*NSC + tid];
    __syncthreads();

    const float4* f0 = (const float4*)(g_f0t + (size_t)b*HW*NC);
    const uint4*  f1 = (const uint4*)(g_fht + (size_t)(0*NB + b)*HW*(NC/2)) + cl;
    const uint4*  f2 = (const uint4*)(g_fht + (size_t)(1*NB + b)*HW*(NC/2)) + cl;

    // ref channels 8*cl .. 8*cl+7
    float r0[8];
    {
        float4 a = f0[pix*16 + cl*2];
        float4 c = f0[pix*16 + cl*2 + 1];
        r0[0]=a.x; r0[1]=a.y; r0[2]=a.z; r0[3]=a.w;
        r0[4]=c.x; r0[5]=c.y; r0[6]=c.z; r0[7]=c.w;
    }
    const float d0 = depth_init[b*HW + pix];

    // s-invariant homography row vectors
    const float* P1 = g_proj[0*NB + b];
    const float* P2 = g_proj[1*NB + b];
    const float m10 = P1[0]*fx + P1[1]*fy + P1[2];
    const float m11 = P1[3]*fx + P1[4]*fy + P1[5];
    const float m12 = P1[6]*fx + P1[7]*fy + P1[8];
    const float t10 = P1[9],  t11 = P1[10], t12 = P1[11];
    const float m20 = P2[0]*fx + P2[1]*fy + P2[2];
    const float m21 = P2[3]*fx + P2[4]*fy + P2[5];
    const float m22 = P2[6]*fx + P2[7]*fy + P2[8];
    const float t20 = P2[9],  t21 = P2[10], t22 = P2[11];

    const float CX = (float)NW / (float)(NW-1);
    const float CY = (float)NH / (float)(NH-1);

    #pragma unroll 1
    for (int s = 0; s < NSC; s++) {
        const float d = d0 * s_scale[s];
        float wt[8];
        int   of[8];

        #pragma unroll
        for (int vv = 0; vv < 2; vv++) {
            float px = vv ? fmaf(m20, d, t20) : fmaf(m10, d, t10);
            float py = vv ? fmaf(m21, d, t21) : fmaf(m11, d, t11);
            float pz = vv ? fmaf(m22, d, t22) : fmaf(m12, d, t12);
            float rz = __fdividef(1.0f, pz);
            float ix = fmaf(px*rz, CX, -0.5f);
            float iy = fmaf(py*rz, CY, -0.5f);
            float x0f = floorf(ix), y0f = floorf(iy);
            float x1f = x0f + 1.0f, y1f = y0f + 1.0f;
            float wx1 = ix - x0f, wx0 = 1.0f - wx1;
            float wy1 = iy - y0f, wy0 = 1.0f - wy1;
            float vx0 = (x0f >= 0.0f && x0f <= (float)(NW-1)) ? 1.0f : 0.0f;
            float vx1 = (x1f >= 0.0f && x1f <= (float)(NW-1)) ? 1.0f : 0.0f;
            float vy0 = (y0f >= 0.0f && y0f <= (float)(NH-1)) ? 1.0f : 0.0f;
            float vy1 = (y1f >= 0.0f && y1f <= (float)(NH-1)) ? 1.0f : 0.0f;
            int x0 = (int)fminf(fmaxf(x0f, 0.0f), (float)(NW-1));
            int x1 = (int)fminf(fmaxf(x1f, 0.0f), (float)(NW-1));
            int y0 = (int)fminf(fmaxf(y0f, 0.0f), (float)(NH-1));
            int y1 = (int)fminf(fmaxf(y1f, 0.0f), (float)(NH-1));
            // uint4 index granularity: 8 uint4 per pixel row of 64 fp16 ch
            wt[vv*4+0] = wx0*wy0*vx0*vy0;  of[vv*4+0] = ((y0<<7) + x0) << 3;
            wt[vv*4+1] = wx1*wy0*vx1*vy0;  of[vv*4+1] = ((y0<<7) + x1) << 3;
            wt[vv*4+2] = wx0*wy1*vx0*vy1;  of[vv*4+2] = ((y1<<7) + x0) << 3;
            wt[vv*4+3] = wx1*wy1*vx1*vy1;  of[vv*4+3] = ((y1<<7) + x1) << 3;
        }

        // -- view 1 interpolate --
        float s1[8] = {0.f,0.f,0.f,0.f,0.f,0.f,0.f,0.f};
        #pragma unroll
        for (int t = 0; t < 4; t++) {
            uint4 q = f1[of[t]];
            float ww = wt[t];
            float2 h0 = __half22float2(*(const __half2*)&q.x);
            float2 h1 = __half22float2(*(((const __half2*)&q.x)+1));
            float2 h2 = __half22float2(*(const __half2*)&q.z);
            float2 h3 = __half22float2(*(((const __half2*)&q.z)+1));
            s1[0]=fmaf(h0.x,ww,s1[0]); s1[1]=fmaf(h0.y,ww,s1[1]);
            s1[2]=fmaf(h1.x,ww,s1[2]); s1[3]=fmaf(h1.y,ww,s1[3]);
            s1[4]=fmaf(h2.x,ww,s1[4]); s1[5]=fmaf(h2.y,ww,s1[5]);
            s1[6]=fmaf(h3.x,ww,s1[6]); s1[7]=fmaf(h3.y,ww,s1[7]);
        }
        float r1[8];
        float acc1 = 0.0f;
        #pragma unroll
        for (int c = 0; c < 8; c++) {
            r1[c] = r0[c] - s1[c];
            acc1 = fmaf(r1[c], r1[c], acc1);
        }

        // -- view 2 interpolate --
        float s2[8] = {0.f,0.f,0.f,0.f,0.f,0.f,0.f,0.f};
        #pragma unroll
        for (int t = 0; t < 4; t++) {
            uint4 q = f2[of[4+t]];
            float ww = wt[4+t];
            float2 h0 = __half22float2(*(const __half2*)&q.x);
            float2 h1 = __half22float2(*(((const __half2*)&q.x)+1));
            float2 h2 = __half22float2(*(const __half2*)&q.z);
            float2 h3 = __half22float2(*(((const __half2*)&q.z)+1));
            s2[0]=fmaf(h0.x,ww,s2[0]); s2[1]=fmaf(h0.y,ww,s2[1]);
            s2[2]=fmaf(h1.x,ww,s2[2]); s2[3]=fmaf(h1.y,ww,s2[3]);
            s2[4]=fmaf(h2.x,ww,s2[4]); s2[5]=fmaf(h2.y,ww,s2[5]);
            s2[6]=fmaf(h3.x,ww,s2[6]); s2[7]=fmaf(h3.y,ww,s2[7]);
        }
        float acc2 = 0.0f;
        #pragma unroll
        for (int c = 0; c < 8; c++) {
            float r2 = r1[c] - s2[c];
            acc2 = fmaf(r2, r2, acc2);
        }

        // reduce across 8 channel lanes
        #pragma unroll
        for (int o = 4; o > 0; o >>= 1) {
            acc1 += __shfl_xor_sync(0xffffffffu, acc1, o);
            acc2 += __shfl_xor_sync(0xffffffffu, acc2, o);
        }
        float cst = sqrtf(acc1) + sqrtf(acc2);
        cst += __shfl_xor_sync(0xffffffffu, cst, 8);
        cst += __shfl_xor_sync(0xffffffffu, cst, 16);
        if (l == 0) s_part[s][w] = cst;
    }

    __syncthreads();
    if (tid < NSC) {
        float v = 0.0f;
        #pragma unroll
        for (int i = 0; i < 8; i++) v += s_part[tid][i];
        g_partial[(b*NSC + tid)*GRIDX + blockIdx.x] = v;
    }
}

// ---------------------------------------------------------------------------
// Parallel partial reduction: one block per (b,s), 128 threads x float4 = 512.
// ---------------------------------------------------------------------------
__global__ void __launch_bounds__(128) k_reduce() {
    const int s = blockIdx.x;
    const int b = blockIdx.y;
    const float4* p = (const float4*)(g_partial + (b*NSC + s)*GRIDX);
    float4 v4 = p[threadIdx.x];
    float v = v4.x + v4.y + v4.z + v4.w;
    #pragma unroll
    for (int o = 16; o > 0; o >>= 1)
        v += __shfl_xor_sync(0xffffffffu, v, o);
    __shared__ float sh[4];
    if ((threadIdx.x & 31) == 0) sh[threadIdx.x >> 5] = v;
    __syncthreads();
    if (threadIdx.x == 0)
        g_cost[b*NSC + s] = (sh[0] + sh[1] + sh[2] + sh[3]) * (1.0f / (2.0f * (float)HW));
}

// ---------------------------------------------------------------------------
// Final: softmax over scales, weighted sum. 64 threads.
// ---------------------------------------------------------------------------
__global__ void k_final(const float* __restrict__ scale_hypo, float* __restrict__ out) {
    int t = threadIdx.x;
    if (t >= NB*NSC) return;
    int b = t >> 5;
    int s = t & 31;

    float cost = g_cost[b*NSC + s];
    float m = cost;
    #pragma unroll
    for (int o = 16; o > 0; o >>= 1)
        m = fmaxf(m, __shfl_xor_sync(0xffffffffu, m, o));
    float e = expf(cost - m);
    float sc = scale_hypo[b*NSC + s];
    float den = e, num = e * sc;
    #pragma unroll
    for (int o = 16; o > 0; o >>= 1) {
        den += __shfl_xor_sync(0xffffffffu, den, o);
        num += __shfl_xor_sync(0xffffffffu, num, o);
    }
    if (s == 0) out[b] = num / den;
}

extern "C" void kernel_launch(void* const* d_in, const int* in_sizes, int n_in,
                              void* d_out, int out_size) {
    const float* feat  = (const float*)d_in[0];   // (V,B,C,H,W)
    const float* intr  = (const float*)d_in[1];   // (V,B,3,3)
    const float* c2w   = (const float*)d_in[2];   // (V,B,4,4)
    const float* scale = (const float*)d_in[3];   // (B,NS)
    const float* depth = (const float*)d_in[4];   // (B,H,W)
    float* out = (float*)d_out;                   // (B,)

    k_prep<<<1, 32>>>(intr, c2w);
    dim3 trg(HW/32, NV*NB);
    k_tr<<<trg, 256>>>(feat);
    dim3 grid(GRIDX, NB);
    k_main<<<grid, 256>>>(scale, depth);
    dim3 rg(NSC, NB);
    k_reduce<<<rg, 128>>>();
    k_final<<<1, 64>>>(scale, out);
}

// round 4
// speedup vs baseline: 2.1744x; 1.2245x over previous
#include <cuda_runtime.h>
#include <cuda_fp16.h>
#include <math.h>

#define NV 3
#define NB 2
#define NC 64
#define NSC 32
#define NH 128
#define NW 128
#define HW (NH*NW)
#define PIX_PER_BLK 32              // 256 threads, 8 lanes per pixel
#define GRIDX (HW/PIX_PER_BLK)      // 512

// Allocation-free scratch.
__device__ float   g_proj[(NV-1)*NB][12];             // [v-1][b]: 3x3 M, then t
__device__ float   g_partial[NB*NSC*GRIDX];           // per-block cost partials
__device__ __half2 g_fht[(size_t)NV*NB*HW*(NC/2)];    // all views transposed (V,B,HW,C) fp16

__device__ __forceinline__ void mat3mul(const float* A, const float* B, float* C) {
    #pragma unroll
    for (int i = 0; i < 3; i++)
        #pragma unroll
        for (int j = 0; j < 3; j++)
            C[i*3+j] = A[i*3+0]*B[0*3+j] + A[i*3+1]*B[1*3+j] + A[i*3+2]*B[2*3+j];
}
__device__ __forceinline__ void mat3vec(const float* A, const float* v, float* r) {
    #pragma unroll
    for (int i = 0; i < 3; i++)
        r[i] = A[i*3+0]*v[0] + A[i*3+1]*v[1] + A[i*3+2]*v[2];
}
__device__ __forceinline__ void mat3inv(const float* A, float* Ai) {
    float a=A[0],b=A[1],c=A[2],d=A[3],e=A[4],f=A[5],g=A[6],h=A[7],i=A[8];
    float det = a*(e*i-f*h) - b*(d*i-f*g) + c*(d*h-e*g);
    float inv = 1.0f / det;
    Ai[0] =  (e*i - f*h)*inv; Ai[1] = -(b*i - c*h)*inv; Ai[2] =  (b*f - c*e)*inv;
    Ai[3] = -(d*i - f*g)*inv; Ai[4] =  (a*i - c*g)*inv; Ai[5] = -(a*f - c*d)*inv;
    Ai[6] =  (d*h - e*g)*inv; Ai[7] = -(a*h - b*g)*inv; Ai[8] =  (a*e - b*d)*inv;
}

__device__ __forceinline__ __half2 u2h2(unsigned u) {
    return *reinterpret_cast<__half2*>(&u);
}

// ---------------------------------------------------------------------------
// Transpose (C,HW)->(HW,C) fp16 for all views; homography prep fused into
// block (0,0) threads 0..3.  grid (HW/32, V*B), 256 threads.
// ---------------------------------------------------------------------------
__global__ void __launch_bounds__(256) k_tr(const float* __restrict__ feat,
                                            const float* __restrict__ intr,
                                            const float* __restrict__ c2w) {
    // --- fused homography prep (one block, 4 threads) ---
    if (blockIdx.x == 0 && blockIdx.y == 0 && threadIdx.x < (NV-1)*NB) {
        int tid = threadIdx.x;
        int v = 1 + tid / NB;
        int b = tid % NB;
        const float* Kr = intr + (0*NB + b)*9;
        const float* Tr = c2w  + (0*NB + b)*16;
        const float* Ks = intr + (v*NB + b)*9;
        const float* Ts = c2w  + (v*NB + b)*16;

        float RrT[9], RsT[9], tr[3], ts[3];
        #pragma unroll
        for (int i = 0; i < 3; i++) {
            #pragma unroll
            for (int j = 0; j < 3; j++) {
                RrT[j*3+i] = Tr[i*4+j];
                RsT[j*3+i] = Ts[i*4+j];
            }
            tr[i] = Tr[i*4+3];
            ts[i] = Ts[i*4+3];
        }
        float trw[3], tsw[3], tmp[3];
        mat3vec(RrT, tr, tmp); trw[0]=-tmp[0]; trw[1]=-tmp[1]; trw[2]=-tmp[2];
        mat3vec(RsT, ts, tmp); tsw[0]=-tmp[0]; tsw[1]=-tmp[1]; tsw[2]=-tmp[2];

        float A[9], bref[3], Ai[9];
        mat3mul(Kr, RrT, A);
        mat3vec(Kr, trw, tmp);
        bref[0]=tmp[0]+trw[0]; bref[1]=tmp[1]+trw[1]; bref[2]=tmp[2]+trw[2];
        mat3inv(A, Ai);

        float SM[9], St[3];
        mat3mul(Ks, RsT, SM);
        mat3vec(Ks, tsw, tmp);
        St[0]=tmp[0]+tsw[0]; St[1]=tmp[1]+tsw[1]; St[2]=tmp[2]+tsw[2];

        float M[9], Mb[3];
        mat3mul(SM, Ai, M);
        mat3vec(M, bref, Mb);

        float* o = g_proj[(v-1)*NB + b];
        #pragma unroll
        for (int i = 0; i < 9; i++) o[i] = M[i];
        o[9]  = St[0] - Mb[0];
        o[10] = St[1] - Mb[1];
        o[11] = St[2] - Mb[2];
    }

    // --- transpose ---
    __shared__ float t[NC][33];
    const int vb  = blockIdx.y;
    const int hw0 = blockIdx.x * 32;
    const float* src = feat + (size_t)vb * NC * HW;

    #pragma unroll
    for (int i = threadIdx.x; i < NC*32; i += 256) {
        int c = i >> 5, hw = i & 31;
        t[c][hw] = src[(size_t)c * HW + hw0 + hw];
    }
    __syncthreads();

    __half2* dst = g_fht + (size_t)vb * HW * (NC/2);
    #pragma unroll
    for (int i = threadIdx.x; i < 32*(NC/2); i += 256) {
        int hw = i >> 5, cp = i & 31;
        dst[(size_t)(hw0 + hw) * (NC/2) + cp] =
            __floats2half2_rn(t[2*cp][hw], t[2*cp+1][hw]);
    }
}

// ---------------------------------------------------------------------------
// Main cost-volume kernel. Block = 256 threads = 32 pixels (8 lanes/pixel).
// All feature math in half2 SIMD; tap = ONE 128B line.
// ---------------------------------------------------------------------------
__global__ void __launch_bounds__(256) k_main(const float* __restrict__ scale_hypo,
                                             const float* __restrict__ depth_init) {
    const int b   = blockIdx.y;
    const int tid = threadIdx.x;
    const int w   = tid >> 5;
    const int l   = tid & 31;
    const int pg  = (w << 2) | (l >> 3);        // pixel in block 0..31
    const int cl  = l & 7;                      // channel chunk 0..7 (8 ch each)
    const int pix = blockIdx.x * PIX_PER_BLK + pg;
    const float fx = (float)(pix & (NW-1));
    const float fy = (float)(pix >> 7);

    __shared__ float s_scale[NSC];
    __shared__ float s_part[NSC][8];
    if (tid < NSC) s_scale[tid] = scale_hypo[b*NSC + tid];
    __syncthreads();

    const uint4* f0 = (const uint4*)(g_fht + (size_t)(0*NB + b)*HW*(NC/2)) + cl;
    const uint4* f1 = (const uint4*)(g_fht + (size_t)(1*NB + b)*HW*(NC/2)) + cl;
    const uint4* f2 = (const uint4*)(g_fht + (size_t)(2*NB + b)*HW*(NC/2)) + cl;

    // ref channels 8*cl .. 8*cl+7 as 4x half2
    __half2 r0h[4];
    {
        uint4 q = f0[pix << 3];
        r0h[0] = u2h2(q.x); r0h[1] = u2h2(q.y);
        r0h[2] = u2h2(q.z); r0h[3] = u2h2(q.w);
    }
    const float d0 = depth_init[b*HW + pix];

    // s-invariant homography row vectors
    const float* P1 = g_proj[0*NB + b];
    const float* P2 = g_proj[1*NB + b];
    const float m10 = P1[0]*fx + P1[1]*fy + P1[2];
    const float m11 = P1[3]*fx + P1[4]*fy + P1[5];
    const float m12 = P1[6]*fx + P1[7]*fy + P1[8];
    const float t10 = P1[9],  t11 = P1[10], t12 = P1[11];
    const float m20 = P2[0]*fx + P2[1]*fy + P2[2];
    const float m21 = P2[3]*fx + P2[4]*fy + P2[5];
    const float m22 = P2[6]*fx + P2[7]*fy + P2[8];
    const float t20 = P2[9],  t21 = P2[10], t22 = P2[11];

    const float CX = (float)NW / (float)(NW-1);
    const float CY = (float)NH / (float)(NH-1);

    #pragma unroll 1
    for (int s = 0; s < NSC; s++) {
        const float d = d0 * s_scale[s];
        __half2 wh[8];
        int     of[8];

        #pragma unroll
        for (int vv = 0; vv < 2; vv++) {
            float px = vv ? fmaf(m20, d, t20) : fmaf(m10, d, t10);
            float py = vv ? fmaf(m21, d, t21) : fmaf(m11, d, t11);
            float pz = vv ? fmaf(m22, d, t22) : fmaf(m12, d, t12);
            float rz = __fdividef(1.0f, pz);
            float ix = fmaf(px*rz, CX, -0.5f);
            float iy = fmaf(py*rz, CY, -0.5f);
            float x0f = floorf(ix), y0f = floorf(iy);
            float x1f = x0f + 1.0f, y1f = y0f + 1.0f;
            float wx1 = ix - x0f, wx0 = 1.0f - wx1;
            float wy1 = iy - y0f, wy0 = 1.0f - wy1;
            float vx0 = (x0f >= 0.0f && x0f <= (float)(NW-1)) ? 1.0f : 0.0f;
            float vx1 = (x1f >= 0.0f && x1f <= (float)(NW-1)) ? 1.0f : 0.0f;
            float vy0 = (y0f >= 0.0f && y0f <= (float)(NH-1)) ? 1.0f : 0.0f;
            float vy1 = (y1f >= 0.0f && y1f <= (float)(NH-1)) ? 1.0f : 0.0f;
            int x0 = (int)fminf(fmaxf(x0f, 0.0f), (float)(NW-1));
            int x1 = (int)fminf(fmaxf(x1f, 0.0f), (float)(NW-1));
            int y0 = (int)fminf(fmaxf(y0f, 0.0f), (float)(NH-1));
            int y1 = (int)fminf(fmaxf(y1f, 0.0f), (float)(NH-1));
            wh[vv*4+0] = __float2half2_rn(wx0*wy0*vx0*vy0);  of[vv*4+0] = ((y0<<7) + x0) << 3;
            wh[vv*4+1] = __float2half2_rn(wx1*wy0*vx1*vy0);  of[vv*4+1] = ((y0<<7) + x1) << 3;
            wh[vv*4+2] = __float2half2_rn(wx0*wy1*vx0*vy1);  of[vv*4+2] = ((y1<<7) + x0) << 3;
            wh[vv*4+3] = __float2half2_rn(wx1*wy1*vx1*vy1);  of[vv*4+3] = ((y1<<7) + x1) << 3;
        }

        const __half2 zero = __float2half2_rn(0.0f);

        // -- view 1 interpolate (half2 SIMD) --
        __half2 s1[4] = {zero, zero, zero, zero};
        #pragma unroll
        for (int t = 0; t < 4; t++) {
            uint4 q = f1[of[t]];
            __half2 ww = wh[t];
            s1[0] = __hfma2(u2h2(q.x), ww, s1[0]);
            s1[1] = __hfma2(u2h2(q.y), ww, s1[1]);
            s1[2] = __hfma2(u2h2(q.z), ww, s1[2]);
            s1[3] = __hfma2(u2h2(q.w), ww, s1[3]);
        }
        __half2 r1h[4];
        __half2 acc1h = zero;
        #pragma unroll
        for (int c = 0; c < 4; c++) {
            r1h[c] = __hsub2(r0h[c], s1[c]);
            acc1h = __hfma2(r1h[c], r1h[c], acc1h);
        }

        // -- view 2 interpolate --
        __half2 s2[4] = {zero, zero, zero, zero};
        #pragma unroll
        for (int t = 0; t < 4; t++) {
            uint4 q = f2[of[4+t]];
            __half2 ww = wh[4+t];
            s2[0] = __hfma2(u2h2(q.x), ww, s2[0]);
            s2[1] = __hfma2(u2h2(q.y), ww, s2[1]);
            s2[2] = __hfma2(u2h2(q.z), ww, s2[2]);
            s2[3] = __hfma2(u2h2(q.w), ww, s2[3]);
        }
        __half2 acc2h = zero;
        #pragma unroll
        for (int c = 0; c < 4; c++) {
            __half2 r2 = __hsub2(r1h[c], s2[c]);
            acc2h = __hfma2(r2, r2, acc2h);
        }

        float2 a1 = __half22float2(acc1h);
        float2 a2 = __half22float2(acc2h);
        float acc1 = a1.x + a1.y;
        float acc2 = a2.x + a2.y;

        // reduce across 8 channel lanes
        #pragma unroll
        for (int o = 4; o > 0; o >>= 1) {
            acc1 += __shfl_xor_sync(0xffffffffu, acc1, o);
            acc2 += __shfl_xor_sync(0xffffffffu, acc2, o);
        }
        float cst = sqrtf(acc1) + sqrtf(acc2);
        cst += __shfl_xor_sync(0xffffffffu, cst, 8);
        cst += __shfl_xor_sync(0xffffffffu, cst, 16);
        if (l == 0) s_part[s][w] = cst;
    }

    __syncthreads();
    if (tid < NSC) {
        float v = 0.0f;
        #pragma unroll
        for (int i = 0; i < 8; i++) v += s_part[tid][i];
        g_partial[(b*NSC + tid)*GRIDX + blockIdx.x] = v;
    }
}

// ---------------------------------------------------------------------------
// Fused reduce + softmax. grid = NB, 1024 threads: warp s reduces 512
// partials of scale s, then warp 0 does softmax + weighted sum.
// ---------------------------------------------------------------------------
__global__ void __launch_bounds__(1024) k_redfin(const float* __restrict__ scale_hypo,
                                                float* __restrict__ out) {
    const int b    = blockIdx.x;
    const int wid  = threadIdx.x >> 5;   // scale index
    const int lane = threadIdx.x & 31;

    const float4* p = (const float4*)(g_partial + (b*NSC + wid)*GRIDX);
    float v = 0.0f;
    #pragma unroll
    for (int i = 0; i < 4; i++) {
        float4 t = p[lane + 32*i];
        v += t.x + t.y + t.z + t.w;
    }
    #pragma unroll
    for (int o = 16; o > 0; o >>= 1)
        v += __shfl_xor_sync(0xffffffffu, v, o);

    __shared__ float sc[NSC];
    if (lane == 0) sc[wid] = v * (1.0f / (2.0f * (float)HW));
    __syncthreads();

    if (wid == 0) {
        float cost = sc[lane];
        float m = cost;
        #pragma unroll
        for (int o = 16; o > 0; o >>= 1)
            m = fmaxf(m, __shfl_xor_sync(0xffffffffu, m, o));
        float e = expf(cost - m);
        float shp = scale_hypo[b*NSC + lane];
        float den = e, num = e * shp;
        #pragma unroll
        for (int o = 16; o > 0; o >>= 1) {
            den += __shfl_xor_sync(0xffffffffu, den, o);
            num += __shfl_xor_sync(0xffffffffu, num, o);
        }
        if (lane == 0) out[b] = num / den;
    }
}

extern "C" void kernel_launch(void* const* d_in, const int* in_sizes, int n_in,
                              void* d_out, int out_size) {
    const float* feat  = (const float*)d_in[0];   // (V,B,C,H,W)
    const float* intr  = (const float*)d_in[1];   // (V,B,3,3)
    const float* c2w   = (const float*)d_in[2];   // (V,B,4,4)
    const float* scale = (const float*)d_in[3];   // (B,NS)
    const float* depth = (const float*)d_in[4];   // (B,H,W)
    float* out = (float*)d_out;                   // (B,)

    dim3 trg(HW/32, NV*NB);
    k_tr<<<trg, 256>>>(feat, intr, c2w);
    dim3 grid(GRIDX, NB);
    k_main<<<grid, 256>>>(scale, depth);
    k_redfin<<<NB, 1024>>>(scale, out);
}